// round 7
// baseline (speedup 1.0000x reference)
#include <cuda_runtime.h>
#include <cuda_bf16.h>
#include <math.h>
#include <stdint.h>

#define ACT_NONE 0
#define ACT_RELU 1
#define ACT_TANH 2
#define ACT_SIG  3

// ---- scratch buffer partition (floats) ----
constexpr size_t N_X1   = 8ull*16*256*256;
constexpr size_t N_P1   = 8ull*16*128*128;
constexpr size_t N_X2   = 8ull*32*128*128;
constexpr size_t N_P2   = 8ull*32*64*64;
constexpr size_t N_X3   = 8ull*32*64*64;
constexpr size_t N_P3   = 8ull*32*32*32;
constexpr size_t N_X4   = 8ull*32*32*32;
constexpr size_t N_P4   = 8ull*32*16*16;
constexpr size_t N_X5   = 8ull*64*16*16;
constexpr size_t N_U5   = 8ull*64*32*32;
constexpr size_t N_X6   = 8ull*32*32*32;
constexpr size_t N_U6   = 8ull*32*64*64;
constexpr size_t N_X7   = 8ull*32*64*64;
constexpr size_t N_U7   = 8ull*32*128*128;
constexpr size_t N_X8   = 8ull*32*128*128;
constexpr size_t N_U8   = 8ull*32*256*256;
constexpr size_t N_FM   = 8ull*64*256*256;
constexpr size_t N_XIN  = 8ull*16*256*256;
constexpr size_t N_RMAX = 8ull*16*256*256;

constexpr size_t O_X1   = 0;
constexpr size_t O_P1   = O_X1   + N_X1;
constexpr size_t O_X2   = O_P1   + N_P1;
constexpr size_t O_P2   = O_X2   + N_X2;
constexpr size_t O_X3   = O_P2   + N_P2;
constexpr size_t O_P3   = O_X3   + N_X3;
constexpr size_t O_X4   = O_P3   + N_P3;
constexpr size_t O_P4   = O_X4   + N_X4;
constexpr size_t O_X5   = O_P4   + N_P4;
constexpr size_t O_U5   = O_X5   + N_X5;
constexpr size_t O_X6   = O_U5   + N_U5;
constexpr size_t O_U6   = O_X6   + N_X6;
constexpr size_t O_X7   = O_U6   + N_U6;
constexpr size_t O_U7   = O_X7   + N_X7;
constexpr size_t O_X8   = O_U7   + N_U7;
constexpr size_t O_U8   = O_X8   + N_X8;
constexpr size_t O_FM   = O_U8   + N_U8;
constexpr size_t O_XIN  = O_FM   + N_FM;
constexpr size_t O_RMAX = O_XIN  + N_XIN;
constexpr size_t N_TOTAL = O_RMAX + N_RMAX;

__device__ float g_buf[N_TOTAL];

// ---- bf16 helpers ----
__device__ __forceinline__ void bf16_split(float v, uint16_t& hi, uint16_t& lo) {
    __nv_bfloat16 h = __float2bfloat16_rn(v);
    hi = __bfloat16_as_ushort(h);
    lo = __bfloat16_as_ushort(__float2bfloat16_rn(v - __bfloat162float(h)));
}
__device__ __forceinline__ uint32_t pk16(uint16_t e0, uint16_t e1) {
    return (uint32_t)e0 | ((uint32_t)e1 << 16);
}
__device__ __forceinline__ void mma_bf16(float* c, const uint32_t* a,
                                         uint32_t b0, uint32_t b1) {
    asm volatile(
        "mma.sync.aligned.m16n8k16.row.col.f32.bf16.bf16.f32 "
        "{%0,%1,%2,%3}, {%4,%5,%6,%7}, {%8,%9}, {%0,%1,%2,%3};"
        : "+f"(c[0]), "+f"(c[1]), "+f"(c[2]), "+f"(c[3])
        : "r"(a[0]), "r"(a[1]), "r"(a[2]), "r"(a[3]), "r"(b0), "r"(b1));
}

// ===================================================================
// Tensor conv via mma.sync (implicit GEMM, 3-term bf16 split).
// Block = 128 thr / 4 warps = 16x8 pixel tile (M=128). Warp: M=32, all N.
// Input staged in 16-cin groups: halo planes pre-split to bf16 hi/lo in
// smem; weights k-paired bf16x2.  k-slot = g*K*K + ky*K + dx; 16 slots
// per mma chunk (K3: 9 chunks/group, K5: 25, both exact).
// ===================================================================
template<int K, int N, int ACT>
__global__ void __launch_bounds__(128) tconv_kernel(
    const float* __restrict__ inA, int CA,
    const float* __restrict__ inB, int CB,
    const float* __restrict__ wgt, const float* __restrict__ bias,
    float* __restrict__ out, int H, int W, int co0, int Ctot)
{
    constexpr int KK  = K * K;
    constexpr int PAD = K / 2;
    constexpr int SH  = 8 + K - 1;
    constexpr int SW  = 16 + K - 1;
    constexpr int G   = 16;
    constexpr int SLOTS  = G * KK;          // 144 / 400
    constexpr int NCHUNK = SLOTS / 16;      // 9 / 25
    constexpr int TP2    = SLOTS / 2;       // k-pairs
    constexpr int NT     = N / 8;

    __shared__ uint16_t s_hi[G * SH * SW];
    __shared__ uint16_t s_lo[G * SH * SW];
    __shared__ uint32_t s_bh[TP2 * N];
    __shared__ uint32_t s_bl[TP2 * N];

    const int tid  = threadIdx.x;
    const int wid  = tid >> 5;
    const int lane = tid & 31;
    const int ql   = lane & 3;      // quad col
    const int qr   = lane >> 2;     // quad row 0..7
    const int x0 = blockIdx.x * 16, y0 = blockIdx.y * 8, b = blockIdx.z;
    const int Cin = CA + CB;
    const size_t HW = (size_t)H * W;

    float acc[2][NT][4];
#pragma unroll
    for (int mt = 0; mt < 2; mt++)
#pragma unroll
        for (int nt = 0; nt < NT; nt++)
#pragma unroll
            for (int i = 0; i < 4; i++) acc[mt][nt][i] = 0.f;

    for (int g0 = 0; g0 < Cin; g0 += G) {
        __syncthreads();
        // ---- stage halo planes, split to bf16 hi/lo ----
        for (int idx = tid; idx < G * SH * SW; idx += 128) {
            int g  = idx / (SH * SW);
            int r  = idx - g * (SH * SW);
            int iy = r / SW, ix = r - iy * SW;
            int cin = g0 + g;
            float v = 0.f;
            if (cin < Cin) {
                int gy = y0 + iy - PAD, gx = x0 + ix - PAD;
                if ((unsigned)gy < (unsigned)H && (unsigned)gx < (unsigned)W) {
                    const float* src = (cin < CA)
                        ? inA + ((size_t)b * CA + cin) * HW
                        : inB + ((size_t)b * CB + (cin - CA)) * HW;
                    v = src[(size_t)gy * W + gx];
                }
            }
            uint16_t h, l;
            bf16_split(v, h, l);
            s_hi[idx] = h;
            s_lo[idx] = l;
        }
        // ---- stage weights as k-paired bf16x2 (hi / lo) ----
        for (int idx = tid; idx < N * TP2; idx += 128) {
            int n = idx / TP2;
            int p = idx - n * TP2;
            uint16_t h0, l0, h1, l1;
            float w0 = 0.f, w1 = 0.f;
            {
                int k = 2 * p;
                int g = k / KK, t = k - g * KK, cin = g0 + g;
                if (cin < Cin)
                    w0 = wgt[((size_t)(co0 + n) * Cin + cin) * KK + t];
                k = 2 * p + 1;
                g = k / KK; t = k - g * KK; cin = g0 + g;
                if (cin < Cin)
                    w1 = wgt[((size_t)(co0 + n) * Cin + cin) * KK + t];
            }
            bf16_split(w0, h0, l0);
            bf16_split(w1, h1, l1);
            s_bh[p * N + n] = pk16(h0, h1);
            s_bl[p * N + n] = pk16(l0, l1);
        }
        __syncthreads();

        // ---- compute: NCHUNK k16 chunks ----
        const int baseL0 = ((2 * wid + 0) * SW + qr);   // mt=0 cell base
        const int baseL1 = ((2 * wid + 1) * SW + qr);   // mt=1 cell base
#pragma unroll
        for (int ck = 0; ck < NCHUNK; ck++) {
            // 4 k positions this lane needs: k0, k0+1, k0+8, k0+9
            int kk0 = ck * 16 + 2 * ql;
            int off[4];
#pragma unroll
            for (int e = 0; e < 4; e++) {
                int kpos = kk0 + (e >> 1) * 8 + (e & 1);
                int g = kpos / KK, t = kpos - g * KK;
                int ky = t / K, dx = t - ky * K;
                off[e] = (g * SH + ky) * SW + dx;
            }
            uint32_t aH[2][4], aL[2][4];
#pragma unroll
            for (int mt = 0; mt < 2; mt++) {
                int bse = (mt == 0) ? baseL0 : baseL1;
                // a0: rows qr, k pair 0-1 ; a1: rows qr+8 ; a2/a3: k+8
                aH[mt][0] = pk16(s_hi[bse + off[0]],     s_hi[bse + off[1]]);
                aH[mt][1] = pk16(s_hi[bse + 8 + off[0]], s_hi[bse + 8 + off[1]]);
                aH[mt][2] = pk16(s_hi[bse + off[2]],     s_hi[bse + off[3]]);
                aH[mt][3] = pk16(s_hi[bse + 8 + off[2]], s_hi[bse + 8 + off[3]]);
                aL[mt][0] = pk16(s_lo[bse + off[0]],     s_lo[bse + off[1]]);
                aL[mt][1] = pk16(s_lo[bse + 8 + off[0]], s_lo[bse + 8 + off[1]]);
                aL[mt][2] = pk16(s_lo[bse + off[2]],     s_lo[bse + off[3]]);
                aL[mt][3] = pk16(s_lo[bse + 8 + off[2]], s_lo[bse + 8 + off[3]]);
            }
#pragma unroll
            for (int nt = 0; nt < NT; nt++) {
                uint32_t bh0 = s_bh[(ck * 8 + ql) * N + nt * 8 + qr];
                uint32_t bh1 = s_bh[(ck * 8 + 4 + ql) * N + nt * 8 + qr];
                uint32_t bl0 = s_bl[(ck * 8 + ql) * N + nt * 8 + qr];
                uint32_t bl1 = s_bl[(ck * 8 + 4 + ql) * N + nt * 8 + qr];
#pragma unroll
                for (int mt = 0; mt < 2; mt++) {
                    mma_bf16(acc[mt][nt], aH[mt], bh0, bh1);
                    mma_bf16(acc[mt][nt], aH[mt], bl0, bl1);
                    mma_bf16(acc[mt][nt], aL[mt], bh0, bh1);
                }
            }
        }
    }

    // ---- epilogue ----
#pragma unroll
    for (int mt = 0; mt < 2; mt++) {
        int my = 2 * wid + mt;
        int gy = y0 + my;
#pragma unroll
        for (int nt = 0; nt < NT; nt++) {
#pragma unroll
            for (int i = 0; i < 4; i++) {
                int col = nt * 8 + 2 * ql + (i & 1);
                int gx  = x0 + qr + ((i >> 1) ? 8 : 0);
                int co  = co0 + col;
                float s = acc[mt][nt][i] + bias[co];
                if (ACT == ACT_RELU)      s = fmaxf(s, 0.f);
                else if (ACT == ACT_TANH) s = tanhf(s);
                else if (ACT == ACT_SIG)  s = 1.f / (1.f + expf(-s));
                out[((size_t)b * Ctot + co) * HW + (size_t)gy * W + gx] = s;
            }
        }
    }
}

// ===================================================================
// Scalar conv (R3 proven) for small deep layers.
// ===================================================================
template<int K, int COC, int ACT, int RPT>
__global__ void __launch_bounds__(128) conv_kernel(
    const float* __restrict__ inA, int CA,
    const float* __restrict__ inB, int CB,
    const float* __restrict__ wgt, const float* __restrict__ bias,
    float* __restrict__ out, int H, int W, int nChunk, int Ctot)
{
    constexpr int KK = K * K, PAD = K / 2, TH = 8 * RPT;
    constexpr int SW = (K == 3) ? 18 : 22;
    constexpr int SH = TH + K - 1;
    __shared__ float s_in[SH * SW];
    __shared__ __align__(16) float s_w[KK * COC];

    const int tx = threadIdx.x & 15, ty = threadIdx.x >> 4;
    const int x0 = blockIdx.x * 16, y0 = blockIdx.y * TH;
    const int z = blockIdx.z;
    const int b = z / nChunk, chunk = z - b * nChunk, co0 = chunk * COC;
    const int Cin = CA + CB;
    const size_t HW = (size_t)H * W;

    float acc[COC * RPT];
#pragma unroll
    for (int i = 0; i < COC * RPT; i++) acc[i] = 0.f;

    for (int cin = 0; cin < Cin; cin++) {
        const float* src = (cin < CA)
            ? inA + ((size_t)b * CA + cin) * HW
            : inB + ((size_t)b * CB + (cin - CA)) * HW;
        __syncthreads();
        for (int i = threadIdx.x; i < SH * SW; i += 128) {
            int iy = i / SW, ix = i - iy * SW;
            int gy = y0 + iy - PAD, gx = x0 + ix - PAD;
            float v = 0.f;
            if ((unsigned)gy < (unsigned)H && (unsigned)gx < (unsigned)W)
                v = src[(size_t)gy * W + gx];
            s_in[i] = v;
        }
        for (int i = threadIdx.x; i < KK * COC; i += 128) {
            int k = i / COC, co = i - k * COC;
            s_w[i] = wgt[((size_t)(co0 + co) * Cin + cin) * KK + k];
        }
        __syncthreads();

#pragma unroll
        for (int k = 0; k < KK; k++) {
            const int ky = k / K, kx = k - ky * K;
            float v[RPT];
#pragma unroll
            for (int r = 0; r < RPT; r++)
                v[r] = s_in[(ty + 8 * r + ky) * SW + tx + kx];
            if (COC % 4 == 0) {
#pragma unroll
                for (int c4 = 0; c4 < COC / 4; c4++) {
                    float4 w = *reinterpret_cast<const float4*>(&s_w[k * COC + 4 * c4]);
#pragma unroll
                    for (int r = 0; r < RPT; r++) {
                        acc[(4 * c4 + 0) * RPT + r] += v[r] * w.x;
                        acc[(4 * c4 + 1) * RPT + r] += v[r] * w.y;
                        acc[(4 * c4 + 2) * RPT + r] += v[r] * w.z;
                        acc[(4 * c4 + 3) * RPT + r] += v[r] * w.w;
                    }
                }
            } else {
#pragma unroll
                for (int co = 0; co < COC; co++) {
                    float w = s_w[k * COC + co];
#pragma unroll
                    for (int r = 0; r < RPT; r++)
                        acc[co * RPT + r] += v[r] * w;
                }
            }
        }
    }

    const int x = x0 + tx;
#pragma unroll
    for (int co = 0; co < COC; co++) {
        float bb = bias[co0 + co];
        size_t cbase = ((size_t)b * Ctot + co0 + co) * HW;
#pragma unroll
        for (int r = 0; r < RPT; r++) {
            float s = acc[co * RPT + r] + bb;
            if (ACT == ACT_RELU)      s = fmaxf(s, 0.f);
            else if (ACT == ACT_TANH) s = tanhf(s);
            else if (ACT == ACT_SIG)  s = 1.f / (1.f + expf(-s));
            out[cbase + (size_t)(y0 + ty + 8 * r) * W + x] = s;
        }
    }
}

__global__ void maxpool_kernel(const float* __restrict__ in,
                               float* __restrict__ out, int n, int Ho, int Wo)
{
    int idx = blockIdx.x * 256 + threadIdx.x;
    if (idx >= n) return;
    int x = idx % Wo, t = idx / Wo, y = t % Ho, bc = t / Ho;
    int Wi = Wo * 2;
    const float* p = in + ((size_t)bc * (Ho * 2) + 2 * y) * Wi + 2 * x;
    out[idx] = fmaxf(fmaxf(p[0], p[1]), fmaxf(p[Wi], p[Wi + 1]));
}

__global__ void upsample_kernel(const float* __restrict__ in,
                                float* __restrict__ out, int n, int Hi, int Wi)
{
    int idx = blockIdx.x * 256 + threadIdx.x;
    if (idx >= n) return;
    int Wo = Wi * 2, Ho = Hi * 2;
    int x = idx % Wo, t = idx / Wo, y = t % Ho, bc = t / Ho;
    int xi = x >> 1, yi = y >> 1;
    int xa, xb; float wxa;
    if (x & 1) { xa = xi; xb = min(xi + 1, Wi - 1); wxa = 0.75f; }
    else       { xa = max(xi - 1, 0); xb = xi;      wxa = 0.25f; }
    int ya, yb; float wya;
    if (y & 1) { ya = yi; yb = min(yi + 1, Hi - 1); wya = 0.75f; }
    else       { ya = max(yi - 1, 0); yb = yi;      wya = 0.25f; }
    const float* p = in + (size_t)bc * Hi * Wi;
    float r0 = wxa * p[ya * Wi + xa] + (1.f - wxa) * p[ya * Wi + xb];
    float r1 = wxa * p[yb * Wi + xa] + (1.f - wxa) * p[yb * Wi + xb];
    out[idx] = wya * r0 + (1.f - wya) * r1;
}

__global__ void lrnn_h_kernel(const float* __restrict__ xin,
                              const float* __restrict__ fm,
                              float* __restrict__ out)
{
    int r = blockIdx.x * 256 + threadIdx.x;
    if (r >= 8 * 16 * 256) return;
    int y = r & 255, c = (r >> 8) & 15, b = r >> 12;
    const float* X  = xin + (((size_t)b * 16 + c) << 16) + (size_t)y * 256;
    const float* P0 = fm  + (((size_t)b * 64 + c)      << 16) + (size_t)y * 256;
    const float* P2 = fm  + (((size_t)b * 64 + 32 + c) << 16) + (size_t)y * 256;
    float* O        = out + (((size_t)b * 16 + c) << 16) + (size_t)y * 256;
    float h0 = 0.f, h1 = 0.f, h2 = 0.f, h3 = 0.f;
    for (int k = 0; k < 256; k++) {
        int j = 255 - k;
        float xf = X[k], xb = X[j];
        float p0 = P0[k], p1 = P2[k], p2 = P0[j], p3 = P2[j];
        h0 = xf + p0 * (h0 - xf);
        h1 = xf + p1 * (h1 - xf);
        h2 = xb + p2 * (h2 - xb);
        h3 = xb + p3 * (h3 - xb);
        O[k] = fmaxf(fmaxf(h0, h1), fmaxf(h2, h3));
    }
}

__global__ void lrnn_v_kernel(const float* __restrict__ xin,
                              const float* __restrict__ fm,
                              float* __restrict__ out)
{
    int r = blockIdx.x * 256 + threadIdx.x;
    if (r >= 8 * 16 * 256) return;
    int x = r & 255, c = (r >> 8) & 15, b = r >> 12;
    const float* X  = xin + (((size_t)b * 16 + c) << 16) + x;
    const float* P1 = fm  + (((size_t)b * 64 + 16 + c) << 16) + x;
    const float* P3 = fm  + (((size_t)b * 64 + 48 + c) << 16) + x;
    float* O        = out + (((size_t)b * 16 + c) << 16) + x;
    float h0 = 0.f, h1 = 0.f, h2 = 0.f, h3 = 0.f;
    for (int k = 0; k < 256; k++) {
        int ko = k << 8, jo = (255 - k) << 8;
        float xf = X[ko], xb = X[jo];
        float p0 = P1[ko], p1 = P3[ko], p2 = P1[jo], p3 = P3[jo];
        h0 = xf + p0 * (h0 - xf);
        h1 = xf + p1 * (h1 - xf);
        h2 = xb + p2 * (h2 - xb);
        h3 = xb + p3 * (h3 - xb);
        float m = fmaxf(fmaxf(h0, h1), fmaxf(h2, h3));
        O[ko] = fmaxf(O[ko], m);
    }
}

extern "C" void kernel_launch(void* const* d_in, const int* in_sizes, int n_in,
                              void* d_out, int out_size)
{
    const float* img = (const float*)d_in[0];
    const float* w1 = (const float*)d_in[1],  *b1 = (const float*)d_in[2];
    const float* w2 = (const float*)d_in[3],  *b2 = (const float*)d_in[4];
    const float* w3 = (const float*)d_in[5],  *b3 = (const float*)d_in[6];
    const float* w4 = (const float*)d_in[7],  *b4 = (const float*)d_in[8];
    const float* w5 = (const float*)d_in[9],  *b5 = (const float*)d_in[10];
    const float* w6 = (const float*)d_in[11], *b6 = (const float*)d_in[12];
    const float* w7 = (const float*)d_in[13], *b7 = (const float*)d_in[14];
    const float* w8 = (const float*)d_in[15], *b8 = (const float*)d_in[16];
    const float* w9 = (const float*)d_in[17], *b9 = (const float*)d_in[18];
    const float* wi = (const float*)d_in[19], *bi = (const float*)d_in[20];
    const float* wo = (const float*)d_in[21], *bo = (const float*)d_in[22];
    float* outp = (float*)d_out;

    float* buf = nullptr;
    cudaGetSymbolAddress((void**)&buf, g_buf);
    float* X1 = buf + O_X1;  float* P1 = buf + O_P1;
    float* X2 = buf + O_X2;  float* P2 = buf + O_P2;
    float* X3 = buf + O_X3;  float* P3 = buf + O_P3;
    float* X4 = buf + O_X4;  float* P4 = buf + O_P4;
    float* X5 = buf + O_X5;  float* U5 = buf + O_U5;
    float* X6 = buf + O_X6;  float* U6 = buf + O_U6;
    float* X7 = buf + O_X7;  float* U7 = buf + O_U7;
    float* X8 = buf + O_X8;  float* U8 = buf + O_U8;
    float* FM = buf + O_FM;  float* XIN = buf + O_XIN;
    float* RMAX = buf + O_RMAX;

    auto tg = [](int W, int H) { return dim3(W / 16, H / 8, 8); };
    auto cgrid = [](int W, int H, int RPT, int nChunk) {
        return dim3(W / 16, H / (8 * RPT), 8 * nChunk);
    };
    auto eg = [](size_t n) { return dim3((unsigned)((n + 255) / 256)); };

    // encoder
    tconv_kernel<5,16,ACT_RELU><<<tg(256,256),128>>>(img,15, nullptr,0, w1,b1, X1, 256,256, 0,16);
    maxpool_kernel<<<eg(N_P1),256>>>(X1, P1, (int)N_P1, 128,128);
    tconv_kernel<3,32,ACT_RELU><<<tg(128,128),128>>>(P1,16, nullptr,0, w2,b2, X2, 128,128, 0,32);
    maxpool_kernel<<<eg(N_P2),256>>>(X2, P2, (int)N_P2, 64,64);
    tconv_kernel<3,32,ACT_RELU><<<tg(64,64),128>>>(P2,32, nullptr,0, w3,b3, X3, 64,64, 0,32);
    maxpool_kernel<<<eg(N_P3),256>>>(X3, P3, (int)N_P3, 32,32);
    conv_kernel<3,16,ACT_RELU,1><<<cgrid(32,32,1,2),128>>>(P3,32, nullptr,0, w4,b4, X4, 32,32, 2,32);
    maxpool_kernel<<<eg(N_P4),256>>>(X4, P4, (int)N_P4, 16,16);
    conv_kernel<3,16,ACT_RELU,1><<<cgrid(16,16,1,4),128>>>(P4,32, nullptr,0, w5,b5, X5, 16,16, 4,64);

    // decoder
    upsample_kernel<<<eg(N_U5),256>>>(X5, U5, (int)N_U5, 16,16);
    conv_kernel<3,16,ACT_RELU,1><<<cgrid(32,32,1,2),128>>>(U5,64, X4,32, w6,b6, X6, 32,32, 2,32);
    upsample_kernel<<<eg(N_U6),256>>>(X6, U6, (int)N_U6, 32,32);
    tconv_kernel<3,32,ACT_RELU><<<tg(64,64),128>>>(U6,32, X3,32, w7,b7, X7, 64,64, 0,32);
    upsample_kernel<<<eg(N_U7),256>>>(X7, U7, (int)N_U7, 64,64);
    tconv_kernel<3,32,ACT_RELU><<<tg(128,128),128>>>(U7,32, X2,32, w8,b8, X8, 128,128, 0,32);
    upsample_kernel<<<eg(N_U8),256>>>(X8, U8, (int)N_U8, 128,128);
    tconv_kernel<3,32,ACT_TANH><<<tg(256,256),128>>>(U8,32, X1,16, w9,b9, FM, 256,256, 0,64);
    tconv_kernel<3,32,ACT_TANH><<<tg(256,256),128>>>(U8,32, X1,16, w9,b9, FM, 256,256, 32,64);

    // input projection
    tconv_kernel<3,16,ACT_NONE><<<tg(256,256),128>>>(img,15, nullptr,0, wi,bi, XIN, 256,256, 0,16);

    // spatial RNN
    lrnn_h_kernel<<<128,256>>>(XIN, FM, RMAX);
    lrnn_v_kernel<<<128,256>>>(XIN, FM, RMAX);

    // output conv + sigmoid (scalar)
    conv_kernel<3,3,ACT_SIG,4><<<cgrid(256,256,4,1),128>>>(RMAX,16, nullptr,0, wo,bo, outp, 256,256, 1,3);
}

// round 8
// speedup vs baseline: 1.4471x; 1.4471x over previous
#include <cuda_runtime.h>
#include <cuda_bf16.h>
#include <math.h>
#include <stdint.h>

#define ACT_NONE 0
#define ACT_RELU 1
#define ACT_TANH 2
#define ACT_SIG  3

// ---- scratch buffer partition (floats) ----
constexpr size_t N_X1   = 8ull*16*256*256;
constexpr size_t N_P1   = 8ull*16*128*128;
constexpr size_t N_X2   = 8ull*32*128*128;
constexpr size_t N_P2   = 8ull*32*64*64;
constexpr size_t N_X3   = 8ull*32*64*64;
constexpr size_t N_P3   = 8ull*32*32*32;
constexpr size_t N_X4   = 8ull*32*32*32;
constexpr size_t N_P4   = 8ull*32*16*16;
constexpr size_t N_X5   = 8ull*64*16*16;
constexpr size_t N_U5   = 8ull*64*32*32;
constexpr size_t N_X6   = 8ull*32*32*32;
constexpr size_t N_U6   = 8ull*32*64*64;
constexpr size_t N_X7   = 8ull*32*64*64;
constexpr size_t N_U7   = 8ull*32*128*128;
constexpr size_t N_X8   = 8ull*32*128*128;
constexpr size_t N_U8   = 8ull*32*256*256;
constexpr size_t N_FM   = 8ull*64*256*256;
constexpr size_t N_XIN  = 8ull*16*256*256;
constexpr size_t N_RMAX = 8ull*16*256*256;

constexpr size_t O_X1   = 0;
constexpr size_t O_P1   = O_X1   + N_X1;
constexpr size_t O_X2   = O_P1   + N_P1;
constexpr size_t O_P2   = O_X2   + N_X2;
constexpr size_t O_X3   = O_P2   + N_P2;
constexpr size_t O_P3   = O_X3   + N_X3;
constexpr size_t O_X4   = O_P3   + N_P3;
constexpr size_t O_P4   = O_X4   + N_X4;
constexpr size_t O_X5   = O_P4   + N_P4;
constexpr size_t O_U5   = O_X5   + N_X5;
constexpr size_t O_X6   = O_U5   + N_U5;
constexpr size_t O_U6   = O_X6   + N_X6;
constexpr size_t O_X7   = O_U6   + N_U6;
constexpr size_t O_U7   = O_X7   + N_X7;
constexpr size_t O_X8   = O_U7   + N_U7;
constexpr size_t O_U8   = O_X8   + N_X8;
constexpr size_t O_FM   = O_U8   + N_U8;
constexpr size_t O_XIN  = O_FM   + N_FM;
constexpr size_t O_RMAX = O_XIN  + N_XIN;
constexpr size_t N_TOTAL = O_RMAX + N_RMAX;

__device__ float g_buf[N_TOTAL];

// ---- bf16 helpers ----
__device__ __forceinline__ void bf16_split(float v, uint16_t& hi, uint16_t& lo) {
    __nv_bfloat16 h = __float2bfloat16_rn(v);
    hi = __bfloat16_as_ushort(h);
    lo = __bfloat16_as_ushort(__float2bfloat16_rn(v - __bfloat162float(h)));
}
// channel c -> u16 position within a pixel's 16-chan record, interleaved so
// slot pair (2ql, 2ql+1) == k-chans (2ql,2ql+1) and (2ql+8, 2ql+9).
__device__ __forceinline__ int idx16(int c) {
    return (c < 8) ? (((c >> 1) << 2) + (c & 1))
                   : ((((c - 8) >> 1) << 2) + 2 + ((c - 8) & 1));
}
__device__ __forceinline__ void mma_bf16(float* c, const uint32_t* a,
                                         uint32_t b0, uint32_t b1) {
    asm volatile(
        "mma.sync.aligned.m16n8k16.row.col.f32.bf16.bf16.f32 "
        "{%0,%1,%2,%3}, {%4,%5,%6,%7}, {%8,%9}, {%0,%1,%2,%3};"
        : "+f"(c[0]), "+f"(c[1]), "+f"(c[2]), "+f"(c[3])
        : "r"(a[0]), "r"(a[1]), "r"(a[2]), "r"(a[3]), "r"(b0), "r"(b1));
}

// ===================================================================
// Tensor conv via mma.sync: k-dim = 16 input channels, taps outer loop.
// Halo stored channel-major (interleaved perm, pitch APITCH u16) so each
// A fragment half is one LDS.64; weights per tap stored n-major (pitch
// BPITCH u32) so each B fragment is one LDS.64.
// 3-term bf16 split: xh*wh + xh*wl + xl*wh.
// Block = 128 thr / 4 warps = 16x8 pixel tile; warp wid: rows 2wid,2wid+1.
// ===================================================================
template<int K, int N, int ACT>
__global__ void __launch_bounds__(128) tconv_kernel(
    const float* __restrict__ inA, int CA,
    const float* __restrict__ inB, int CB,
    const float* __restrict__ wgt, const float* __restrict__ bias,
    float* __restrict__ out, int H, int W, int co0, int Ctot)
{
    constexpr int KK   = K * K;
    constexpr int PAD  = K / 2;
    constexpr int SH   = 8 + K - 1;
    constexpr int SWI  = 16 + K - 1;
    constexpr int NPIX = SH * SWI;
    constexpr int APITCH = (K == 3) ? 24 : 20;  // u16 units (48B / 40B)
    constexpr int BPITCH = (K == 3) ? 12 : 8;   // u32 units (48B / 32B)
    constexpr int NT   = N / 8;

    __shared__ __align__(8) uint16_t s_hi[NPIX * APITCH];
    __shared__ __align__(8) uint16_t s_lo[NPIX * APITCH];
    __shared__ __align__(8) uint16_t s_bh[KK * N * BPITCH * 2];
    __shared__ __align__(8) uint16_t s_bl[KK * N * BPITCH * 2];

    const int tid  = threadIdx.x;
    const int wid  = tid >> 5;
    const int lane = tid & 31;
    const int ql   = lane & 3;
    const int qr   = lane >> 2;
    const int x0 = blockIdx.x * 16, y0 = blockIdx.y * 8, b = blockIdx.z;
    const int Cin = CA + CB;
    const size_t HW = (size_t)H * W;

    float acc[2][NT][4];
#pragma unroll
    for (int mt = 0; mt < 2; mt++)
#pragma unroll
        for (int nt = 0; nt < NT; nt++)
#pragma unroll
            for (int i = 0; i < 4; i++) acc[mt][nt][i] = 0.f;

    for (int g0 = 0; g0 < Cin; g0 += 16) {
        __syncthreads();
        // ---- stage halo, channel-major interleaved, bf16 hi/lo ----
        for (int idx = tid; idx < 16 * NPIX; idx += 128) {
            int ch  = idx / NPIX;
            int pix = idx - ch * NPIX;
            int iy = pix / SWI, ix = pix - iy * SWI;
            int cin = g0 + ch;
            float v = 0.f;
            if (cin < Cin) {
                int gy = y0 + iy - PAD, gx = x0 + ix - PAD;
                if ((unsigned)gy < (unsigned)H && (unsigned)gx < (unsigned)W) {
                    const float* src = (cin < CA)
                        ? inA + ((size_t)b * CA + cin) * HW
                        : inB + ((size_t)b * CB + (cin - CA)) * HW;
                    v = src[(size_t)gy * W + gx];
                }
            }
            uint16_t h, l;
            bf16_split(v, h, l);
            int p = pix * APITCH + idx16(ch);
            s_hi[p] = h;
            s_lo[p] = l;
        }
        // ---- stage weights: [tap][n][chan-interleaved] ----
        for (int idx = tid; idx < KK * N * 16; idx += 128) {
            int ch = idx & 15;
            int r  = idx >> 4;
            int n  = r % N;
            int t  = r / N;
            int cin = g0 + ch;
            float w = 0.f;
            if (cin < Cin)
                w = wgt[((size_t)(co0 + n) * Cin + cin) * KK + t];
            uint16_t h, l;
            bf16_split(w, h, l);
            int p = (t * N + n) * (BPITCH * 2) + idx16(ch);
            s_bh[p] = h;
            s_bl[p] = l;
        }
        __syncthreads();

        // ---- compute: KK taps, each one k16 mma set ----
#pragma unroll
        for (int ky = 0; ky < K; ky++)
#pragma unroll
        for (int kx = 0; kx < K; kx++) {
            const int t = ky * K + kx;
            uint32_t aH[2][4], aL[2][4];
#pragma unroll
            for (int mt = 0; mt < 2; mt++) {
                int pixA = (2 * wid + mt + ky) * SWI + (qr + kx);
                uint2 h0 = *reinterpret_cast<const uint2*>(
                    &s_hi[pixA * APITCH + 4 * ql]);
                uint2 h1 = *reinterpret_cast<const uint2*>(
                    &s_hi[(pixA + 8) * APITCH + 4 * ql]);
                uint2 l0 = *reinterpret_cast<const uint2*>(
                    &s_lo[pixA * APITCH + 4 * ql]);
                uint2 l1 = *reinterpret_cast<const uint2*>(
                    &s_lo[(pixA + 8) * APITCH + 4 * ql]);
                aH[mt][0] = h0.x; aH[mt][1] = h1.x;
                aH[mt][2] = h0.y; aH[mt][3] = h1.y;
                aL[mt][0] = l0.x; aL[mt][1] = l1.x;
                aL[mt][2] = l0.y; aL[mt][3] = l1.y;
            }
#pragma unroll
            for (int nt = 0; nt < NT; nt++) {
                uint2 bh = *reinterpret_cast<const uint2*>(
                    &s_bh[(t * N + nt * 8 + qr) * (BPITCH * 2) + 4 * ql]);
                uint2 bl = *reinterpret_cast<const uint2*>(
                    &s_bl[(t * N + nt * 8 + qr) * (BPITCH * 2) + 4 * ql]);
#pragma unroll
                for (int mt = 0; mt < 2; mt++) {
                    mma_bf16(acc[mt][nt], aH[mt], bh.x, bh.y);
                    mma_bf16(acc[mt][nt], aH[mt], bl.x, bl.y);
                    mma_bf16(acc[mt][nt], aL[mt], bh.x, bh.y);
                }
            }
        }
    }

    // ---- epilogue: out pixel x = qr + (i>>1)*8, y = 2wid+mt,
    //      channel co0 + nt*8 + 2ql + (i&1) ----
#pragma unroll
    for (int mt = 0; mt < 2; mt++) {
        int gy = y0 + 2 * wid + mt;
#pragma unroll
        for (int nt = 0; nt < NT; nt++) {
#pragma unroll
            for (int i = 0; i < 4; i++) {
                int co = co0 + nt * 8 + 2 * ql + (i & 1);
                int gx = x0 + qr + ((i >> 1) ? 8 : 0);
                float s = acc[mt][nt][i] + bias[co];
                if (ACT == ACT_RELU)      s = fmaxf(s, 0.f);
                else if (ACT == ACT_TANH) s = tanhf(s);
                else if (ACT == ACT_SIG)  s = 1.f / (1.f + expf(-s));
                out[((size_t)b * Ctot + co) * HW + (size_t)gy * W + gx] = s;
            }
        }
    }
}

// ===================================================================
// Scalar conv (R3 proven) for small deep layers.
// ===================================================================
template<int K, int COC, int ACT, int RPT>
__global__ void __launch_bounds__(128) conv_kernel(
    const float* __restrict__ inA, int CA,
    const float* __restrict__ inB, int CB,
    const float* __restrict__ wgt, const float* __restrict__ bias,
    float* __restrict__ out, int H, int W, int nChunk, int Ctot)
{
    constexpr int KK = K * K, PAD = K / 2, TH = 8 * RPT;
    constexpr int SW = (K == 3) ? 18 : 22;
    constexpr int SH = TH + K - 1;
    __shared__ float s_in[SH * SW];
    __shared__ __align__(16) float s_w[KK * COC];

    const int tx = threadIdx.x & 15, ty = threadIdx.x >> 4;
    const int x0 = blockIdx.x * 16, y0 = blockIdx.y * TH;
    const int z = blockIdx.z;
    const int b = z / nChunk, chunk = z - b * nChunk, co0 = chunk * COC;
    const int Cin = CA + CB;
    const size_t HW = (size_t)H * W;

    float acc[COC * RPT];
#pragma unroll
    for (int i = 0; i < COC * RPT; i++) acc[i] = 0.f;

    for (int cin = 0; cin < Cin; cin++) {
        const float* src = (cin < CA)
            ? inA + ((size_t)b * CA + cin) * HW
            : inB + ((size_t)b * CB + (cin - CA)) * HW;
        __syncthreads();
        for (int i = threadIdx.x; i < SH * SW; i += 128) {
            int iy = i / SW, ix = i - iy * SW;
            int gy = y0 + iy - PAD, gx = x0 + ix - PAD;
            float v = 0.f;
            if ((unsigned)gy < (unsigned)H && (unsigned)gx < (unsigned)W)
                v = src[(size_t)gy * W + gx];
            s_in[i] = v;
        }
        for (int i = threadIdx.x; i < KK * COC; i += 128) {
            int k = i / COC, co = i - k * COC;
            s_w[i] = wgt[((size_t)(co0 + co) * Cin + cin) * KK + k];
        }
        __syncthreads();

#pragma unroll
        for (int k = 0; k < KK; k++) {
            const int ky = k / K, kx = k - ky * K;
            float v[RPT];
#pragma unroll
            for (int r = 0; r < RPT; r++)
                v[r] = s_in[(ty + 8 * r + ky) * SW + tx + kx];
            if (COC % 4 == 0) {
#pragma unroll
                for (int c4 = 0; c4 < COC / 4; c4++) {
                    float4 w = *reinterpret_cast<const float4*>(&s_w[k * COC + 4 * c4]);
#pragma unroll
                    for (int r = 0; r < RPT; r++) {
                        acc[(4 * c4 + 0) * RPT + r] += v[r] * w.x;
                        acc[(4 * c4 + 1) * RPT + r] += v[r] * w.y;
                        acc[(4 * c4 + 2) * RPT + r] += v[r] * w.z;
                        acc[(4 * c4 + 3) * RPT + r] += v[r] * w.w;
                    }
                }
            } else {
#pragma unroll
                for (int co = 0; co < COC; co++) {
                    float w = s_w[k * COC + co];
#pragma unroll
                    for (int r = 0; r < RPT; r++)
                        acc[co * RPT + r] += v[r + 0] * w;
                }
            }
        }
    }

    const int x = x0 + tx;
#pragma unroll
    for (int co = 0; co < COC; co++) {
        float bb = bias[co0 + co];
        size_t cbase = ((size_t)b * Ctot + co0 + co) * HW;
#pragma unroll
        for (int r = 0; r < RPT; r++) {
            float s = acc[co * RPT + r] + bb;
            if (ACT == ACT_RELU)      s = fmaxf(s, 0.f);
            else if (ACT == ACT_TANH) s = tanhf(s);
            else if (ACT == ACT_SIG)  s = 1.f / (1.f + expf(-s));
            out[cbase + (size_t)(y0 + ty + 8 * r) * W + x] = s;
        }
    }
}

__global__ void maxpool_kernel(const float* __restrict__ in,
                               float* __restrict__ out, int n, int Ho, int Wo)
{
    int idx = blockIdx.x * 256 + threadIdx.x;
    if (idx >= n) return;
    int x = idx % Wo, t = idx / Wo, y = t % Ho, bc = t / Ho;
    int Wi = Wo * 2;
    const float* p = in + ((size_t)bc * (Ho * 2) + 2 * y) * Wi + 2 * x;
    out[idx] = fmaxf(fmaxf(p[0], p[1]), fmaxf(p[Wi], p[Wi + 1]));
}

__global__ void upsample_kernel(const float* __restrict__ in,
                                float* __restrict__ out, int n, int Hi, int Wi)
{
    int idx = blockIdx.x * 256 + threadIdx.x;
    if (idx >= n) return;
    int Wo = Wi * 2, Ho = Hi * 2;
    int x = idx % Wo, t = idx / Wo, y = t % Ho, bc = t / Ho;
    int xi = x >> 1, yi = y >> 1;
    int xa, xb; float wxa;
    if (x & 1) { xa = xi; xb = min(xi + 1, Wi - 1); wxa = 0.75f; }
    else       { xa = max(xi - 1, 0); xb = xi;      wxa = 0.25f; }
    int ya, yb; float wya;
    if (y & 1) { ya = yi; yb = min(yi + 1, Hi - 1); wya = 0.75f; }
    else       { ya = max(yi - 1, 0); yb = yi;      wya = 0.25f; }
    const float* p = in + (size_t)bc * Hi * Wi;
    float r0 = wxa * p[ya * Wi + xa] + (1.f - wxa) * p[ya * Wi + xb];
    float r1 = wxa * p[yb * Wi + xa] + (1.f - wxa) * p[yb * Wi + xb];
    out[idx] = wya * r0 + (1.f - wya) * r1;
}

__global__ void lrnn_h_kernel(const float* __restrict__ xin,
                              const float* __restrict__ fm,
                              float* __restrict__ out)
{
    int r = blockIdx.x * 256 + threadIdx.x;
    if (r >= 8 * 16 * 256) return;
    int y = r & 255, c = (r >> 8) & 15, b = r >> 12;
    const float* X  = xin + (((size_t)b * 16 + c) << 16) + (size_t)y * 256;
    const float* P0 = fm  + (((size_t)b * 64 + c)      << 16) + (size_t)y * 256;
    const float* P2 = fm  + (((size_t)b * 64 + 32 + c) << 16) + (size_t)y * 256;
    float* O        = out + (((size_t)b * 16 + c) << 16) + (size_t)y * 256;
    float h0 = 0.f, h1 = 0.f, h2 = 0.f, h3 = 0.f;
    for (int k = 0; k < 256; k++) {
        int j = 255 - k;
        float xf = X[k], xb = X[j];
        float p0 = P0[k], p1 = P2[k], p2 = P0[j], p3 = P2[j];
        h0 = xf + p0 * (h0 - xf);
        h1 = xf + p1 * (h1 - xf);
        h2 = xb + p2 * (h2 - xb);
        h3 = xb + p3 * (h3 - xb);
        O[k] = fmaxf(fmaxf(h0, h1), fmaxf(h2, h3));
    }
}

__global__ void lrnn_v_kernel(const float* __restrict__ xin,
                              const float* __restrict__ fm,
                              float* __restrict__ out)
{
    int r = blockIdx.x * 256 + threadIdx.x;
    if (r >= 8 * 16 * 256) return;
    int x = r & 255, c = (r >> 8) & 15, b = r >> 12;
    const float* X  = xin + (((size_t)b * 16 + c) << 16) + x;
    const float* P1 = fm  + (((size_t)b * 64 + 16 + c) << 16) + x;
    const float* P3 = fm  + (((size_t)b * 64 + 48 + c) << 16) + x;
    float* O        = out + (((size_t)b * 16 + c) << 16) + x;
    float h0 = 0.f, h1 = 0.f, h2 = 0.f, h3 = 0.f;
    for (int k = 0; k < 256; k++) {
        int ko = k << 8, jo = (255 - k) << 8;
        float xf = X[ko], xb = X[jo];
        float p0 = P1[ko], p1 = P3[ko], p2 = P1[jo], p3 = P3[jo];
        h0 = xf + p0 * (h0 - xf);
        h1 = xf + p1 * (h1 - xf);
        h2 = xb + p2 * (h2 - xb);
        h3 = xb + p3 * (h3 - xb);
        float m = fmaxf(fmaxf(h0, h1), fmaxf(h2, h3));
        O[ko] = fmaxf(O[ko], m);
    }
}

extern "C" void kernel_launch(void* const* d_in, const int* in_sizes, int n_in,
                              void* d_out, int out_size)
{
    const float* img = (const float*)d_in[0];
    const float* w1 = (const float*)d_in[1],  *b1 = (const float*)d_in[2];
    const float* w2 = (const float*)d_in[3],  *b2 = (const float*)d_in[4];
    const float* w3 = (const float*)d_in[5],  *b3 = (const float*)d_in[6];
    const float* w4 = (const float*)d_in[7],  *b4 = (const float*)d_in[8];
    const float* w5 = (const float*)d_in[9],  *b5 = (const float*)d_in[10];
    const float* w6 = (const float*)d_in[11], *b6 = (const float*)d_in[12];
    const float* w7 = (const float*)d_in[13], *b7 = (const float*)d_in[14];
    const float* w8 = (const float*)d_in[15], *b8 = (const float*)d_in[16];
    const float* w9 = (const float*)d_in[17], *b9 = (const float*)d_in[18];
    const float* wi = (const float*)d_in[19], *bi = (const float*)d_in[20];
    const float* wo = (const float*)d_in[21], *bo = (const float*)d_in[22];
    float* outp = (float*)d_out;

    float* buf = nullptr;
    cudaGetSymbolAddress((void**)&buf, g_buf);
    float* X1 = buf + O_X1;  float* P1 = buf + O_P1;
    float* X2 = buf + O_X2;  float* P2 = buf + O_P2;
    float* X3 = buf + O_X3;  float* P3 = buf + O_P3;
    float* X4 = buf + O_X4;  float* P4 = buf + O_P4;
    float* X5 = buf + O_X5;  float* U5 = buf + O_U5;
    float* X6 = buf + O_X6;  float* U6 = buf + O_U6;
    float* X7 = buf + O_X7;  float* U7 = buf + O_U7;
    float* X8 = buf + O_X8;  float* U8 = buf + O_U8;
    float* FM = buf + O_FM;  float* XIN = buf + O_XIN;
    float* RMAX = buf + O_RMAX;

    auto tg = [](int W, int H) { return dim3(W / 16, H / 8, 8); };
    auto cgrid = [](int W, int H, int RPT, int nChunk) {
        return dim3(W / 16, H / (8 * RPT), 8 * nChunk);
    };
    auto eg = [](size_t n) { return dim3((unsigned)((n + 255) / 256)); };

    // encoder
    tconv_kernel<5,16,ACT_RELU><<<tg(256,256),128>>>(img,15, nullptr,0, w1,b1, X1, 256,256, 0,16);
    maxpool_kernel<<<eg(N_P1),256>>>(X1, P1, (int)N_P1, 128,128);
    tconv_kernel<3,32,ACT_RELU><<<tg(128,128),128>>>(P1,16, nullptr,0, w2,b2, X2, 128,128, 0,32);
    maxpool_kernel<<<eg(N_P2),256>>>(X2, P2, (int)N_P2, 64,64);
    tconv_kernel<3,32,ACT_RELU><<<tg(64,64),128>>>(P2,32, nullptr,0, w3,b3, X3, 64,64, 0,32);
    maxpool_kernel<<<eg(N_P3),256>>>(X3, P3, (int)N_P3, 32,32);
    conv_kernel<3,16,ACT_RELU,1><<<cgrid(32,32,1,2),128>>>(P3,32, nullptr,0, w4,b4, X4, 32,32, 2,32);
    maxpool_kernel<<<eg(N_P4),256>>>(X4, P4, (int)N_P4, 16,16);
    conv_kernel<3,16,ACT_RELU,1><<<cgrid(16,16,1,4),128>>>(P4,32, nullptr,0, w5,b5, X5, 16,16, 4,64);

    // decoder
    upsample_kernel<<<eg(N_U5),256>>>(X5, U5, (int)N_U5, 16,16);
    conv_kernel<3,16,ACT_RELU,1><<<cgrid(32,32,1,2),128>>>(U5,64, X4,32, w6,b6, X6, 32,32, 2,32);
    upsample_kernel<<<eg(N_U6),256>>>(X6, U6, (int)N_U6, 32,32);
    tconv_kernel<3,32,ACT_RELU><<<tg(64,64),128>>>(U6,32, X3,32, w7,b7, X7, 64,64, 0,32);
    upsample_kernel<<<eg(N_U7),256>>>(X7, U7, (int)N_U7, 64,64);
    tconv_kernel<3,32,ACT_RELU><<<tg(128,128),128>>>(U7,32, X2,32, w8,b8, X8, 128,128, 0,32);
    upsample_kernel<<<eg(N_U8),256>>>(X8, U8, (int)N_U8, 128,128);
    tconv_kernel<3,32,ACT_TANH><<<tg(256,256),128>>>(U8,32, X1,16, w9,b9, FM, 256,256, 0,64);
    tconv_kernel<3,32,ACT_TANH><<<tg(256,256),128>>>(U8,32, X1,16, w9,b9, FM, 256,256, 32,64);

    // input projection
    tconv_kernel<3,16,ACT_NONE><<<tg(256,256),128>>>(img,15, nullptr,0, wi,bi, XIN, 256,256, 0,16);

    // spatial RNN
    lrnn_h_kernel<<<128,256>>>(XIN, FM, RMAX);
    lrnn_v_kernel<<<128,256>>>(XIN, FM, RMAX);

    // output conv + sigmoid (scalar)
    conv_kernel<3,3,ACT_SIG,4><<<cgrid(256,256,4,1),128>>>(RMAX,16, nullptr,0, wo,bo, outp, 256,256, 1,3);
}

// round 10
// speedup vs baseline: 1.7227x; 1.1905x over previous
#include <cuda_runtime.h>
#include <cuda_bf16.h>
#include <math.h>
#include <stdint.h>

#define ACT_NONE 0
#define ACT_RELU 1
#define ACT_TANH 2
#define ACT_SIG  3

// ---- scratch buffer partition (floats) ----
constexpr size_t N_X1   = 8ull*16*256*256;
constexpr size_t N_P1   = 8ull*16*128*128;
constexpr size_t N_X2   = 8ull*32*128*128;
constexpr size_t N_P2   = 8ull*32*64*64;
constexpr size_t N_X3   = 8ull*32*64*64;
constexpr size_t N_P3   = 8ull*32*32*32;
constexpr size_t N_X4   = 8ull*32*32*32;
constexpr size_t N_P4   = 8ull*32*16*16;
constexpr size_t N_X5   = 8ull*64*16*16;
constexpr size_t N_U5   = 8ull*64*32*32;
constexpr size_t N_X6   = 8ull*32*32*32;
constexpr size_t N_U6   = 8ull*32*64*64;
constexpr size_t N_X7   = 8ull*32*64*64;
constexpr size_t N_U7   = 8ull*32*128*128;
constexpr size_t N_X8   = 8ull*32*128*128;
constexpr size_t N_U8   = 8ull*32*256*256;
constexpr size_t N_FM   = 8ull*64*256*256;
constexpr size_t N_XIN  = 8ull*16*256*256;
constexpr size_t N_RMAX = 8ull*16*256*256;
constexpr size_t N_WP   = 262144;            // room for 2 x 131072 u16 planes

constexpr size_t O_X1   = 0;
constexpr size_t O_P1   = O_X1   + N_X1;
constexpr size_t O_X2   = O_P1   + N_P1;
constexpr size_t O_P2   = O_X2   + N_X2;
constexpr size_t O_X3   = O_P2   + N_P2;
constexpr size_t O_P3   = O_X3   + N_X3;
constexpr size_t O_X4   = O_P3   + N_P3;
constexpr size_t O_P4   = O_X4   + N_X4;
constexpr size_t O_X5   = O_P4   + N_P4;
constexpr size_t O_U5   = O_X5   + N_X5;
constexpr size_t O_X6   = O_U5   + N_U5;
constexpr size_t O_U6   = O_X6   + N_X6;
constexpr size_t O_X7   = O_U6   + N_U6;
constexpr size_t O_U7   = O_X7   + N_X7;
constexpr size_t O_X8   = O_U7   + N_U7;
constexpr size_t O_U8   = O_X8   + N_X8;
constexpr size_t O_FM   = O_U8   + N_U8;
constexpr size_t O_XIN  = O_FM   + N_FM;
constexpr size_t O_RMAX = O_XIN  + N_XIN;
constexpr size_t O_WP   = O_RMAX + N_RMAX;
constexpr size_t N_TOTAL = O_WP + N_WP;

__device__ float g_buf[N_TOTAL];

// prepped-weight offsets (u16 units within each plane; all multiples of 2048)
constexpr int WOFF1 = 0;       // conv1: 1g*25*16*16 = 6400
constexpr int WOFF2 = 8192;    // conv2: 1g*9*32*16  = 4608
constexpr int WOFF3 = 16384;   // conv3: 2g*9*32*16  = 9216
constexpr int WOFF7 = 32768;   // conv7: 4g*9*32*16  = 18432 -> fits before 65536? 32768+18432=51200
constexpr int WOFF8 = 53248;   // conv8: 18432 -> ends 71680
constexpr int WOFF9 = 73728;   // conv9: 3g*9*64*16  = 27648 -> ends 101376
constexpr int WOFFI = 104448;  // convi: 1g*9*16*16  = 2304  -> ends 106752
constexpr int WPLANE = 131072; // u16 per plane

// ---- bf16 helpers ----
__device__ __forceinline__ void bf16_split(float v, uint16_t& hi, uint16_t& lo) {
    __nv_bfloat16 h = __float2bfloat16_rn(v);
    hi = __bfloat16_as_ushort(h);
    lo = __bfloat16_as_ushort(__float2bfloat16_rn(v - __bfloat162float(h)));
}
// channel c -> u16 slot within a 16-chan record: pairs (2q,2q+1) at 4q,4q+1
// and (2q+8,2q+9) at 4q+2,4q+3 so one 8-byte load covers a lane's fragment.
__device__ __forceinline__ int idx16(int c) {
    return (c < 8) ? (((c >> 1) << 2) + (c & 1))
                   : ((((c - 8) >> 1) << 2) + 2 + ((c - 8) & 1));
}
__device__ __forceinline__ void mma_bf16(float* c, const uint32_t* a,
                                         uint32_t b0, uint32_t b1) {
    asm volatile(
        "mma.sync.aligned.m16n8k16.row.col.f32.bf16.bf16.f32 "
        "{%0,%1,%2,%3}, {%4,%5,%6,%7}, {%8,%9}, {%0,%1,%2,%3};"
        : "+f"(c[0]), "+f"(c[1]), "+f"(c[2]), "+f"(c[3])
        : "r"(a[0]), "r"(a[1]), "r"(a[2]), "r"(a[3]), "r"(b0), "r"(b1));
}

// ===================================================================
// Weight prep: fp32 OIHW -> [g][tap][n][idx16(ch)] bf16 hi/lo planes.
// Record = 16 u16 = 32 bytes, uint4-aligned.
// ===================================================================
__global__ void prep_w_kernel(const float* __restrict__ wgt,
                              uint16_t* __restrict__ wph,
                              uint16_t* __restrict__ wpl,
                              int Cin, int Cout, int KK, int total)
{
    int idx = blockIdx.x * 256 + threadIdx.x;
    if (idx >= total) return;
    int ch = idx & 15;
    int r  = idx >> 4;
    int n  = r % Cout;
    int r2 = r / Cout;
    int t  = r2 % KK;
    int g  = r2 / KK;
    int cin = g * 16 + ch;
    float w = (cin < Cin) ? wgt[((size_t)n * Cin + cin) * KK + t] : 0.f;
    uint16_t h, l;
    bf16_split(w, h, l);
    int p = ((g * KK + t) * Cout + n) * 16 + idx16(ch);
    wph[p] = h;
    wpl[p] = l;
}

// ===================================================================
// Tensor conv via mma.sync (R8-proven compute): 16x8 pixel tile, 128 thr
// / 4 warps; warp wid handles y-rows 2wid, 2wid+1.  k = 16 input chans;
// taps outer.  A halo channel-major interleaved in smem; B records
// COPIED (uint4) from prepped gmem planes into R8's smem layout.
// 3-term bf16 split: xh*wh + xh*wl + xl*wh.
// ===================================================================
template<int K, int N, int ACT>
__global__ void __launch_bounds__(128) tconv_kernel(
    const float* __restrict__ inA, int CA,
    const float* __restrict__ inB, int CB,
    const uint16_t* __restrict__ wph, const uint16_t* __restrict__ wpl,
    const float* __restrict__ bias,
    float* __restrict__ out, int H, int W, int co0, int Ctot)
{
    constexpr int KK   = K * K;
    constexpr int PAD  = K / 2;
    constexpr int SH   = 8 + K - 1;
    constexpr int SWI  = 16 + K - 1;
    constexpr int NPIX = SH * SWI;
    constexpr int APITCH = (K == 3) ? 24 : 20;  // u16
    constexpr int BP16 = (K == 3) ? 24 : 16;    // u16 pitch per (t,n) record
    constexpr int BPU4 = (K == 3) ? 3  : 2;     // uint4 per record slot
    constexpr int NT   = N / 8;

    __shared__ __align__(16) uint16_t s_hi[NPIX * APITCH];
    __shared__ __align__(16) uint16_t s_lo[NPIX * APITCH];
    __shared__ __align__(16) uint16_t s_bh[KK * N * BP16];
    __shared__ __align__(16) uint16_t s_bl[KK * N * BP16];

    const int tid  = threadIdx.x;
    const int wid  = tid >> 5;
    const int lane = tid & 31;
    const int ql   = lane & 3;
    const int qr   = lane >> 2;
    const int x0 = blockIdx.x * 16, y0 = blockIdx.y * 8, b = blockIdx.z;
    const int Cin = CA + CB;
    const size_t HW = (size_t)H * W;

    float acc[2][NT][4];
#pragma unroll
    for (int mt = 0; mt < 2; mt++)
#pragma unroll
        for (int nt = 0; nt < NT; nt++)
#pragma unroll
            for (int i = 0; i < 4; i++) acc[mt][nt][i] = 0.f;

    const int nG = (Cin + 15) >> 4;
    for (int gi = 0; gi < nG; gi++) {
        const int g0 = gi * 16;
        __syncthreads();
        // ---- stage halo, channel-major interleaved, bf16 hi/lo ----
        for (int idx = tid; idx < 16 * NPIX; idx += 128) {
            int ch  = idx / NPIX;
            int pix = idx - ch * NPIX;
            int iy = pix / SWI, ix = pix - iy * SWI;
            int cin = g0 + ch;
            float v = 0.f;
            if (cin < Cin) {
                int gy = y0 + iy - PAD, gx = x0 + ix - PAD;
                if ((unsigned)gy < (unsigned)H && (unsigned)gx < (unsigned)W) {
                    const float* src = (cin < CA)
                        ? inA + ((size_t)b * CA + cin) * HW
                        : inB + ((size_t)b * CB + (cin - CA)) * HW;
                    v = src[(size_t)gy * W + gx];
                }
            }
            uint16_t h, l;
            bf16_split(v, h, l);
            int p = pix * APITCH + idx16(ch);
            s_hi[p] = h;
            s_lo[p] = l;
        }
        // ---- copy B records (prepped) gmem -> smem, uint4 ----
        {
            const uint4* srcH = reinterpret_cast<const uint4*>(wph);
            const uint4* srcL = reinterpret_cast<const uint4*>(wpl);
            uint4* dstH = reinterpret_cast<uint4*>(s_bh);
            uint4* dstL = reinterpret_cast<uint4*>(s_bl);
            for (int u = tid; u < KK * N * 2; u += 128) {
                int q = u & 1;
                int r = u >> 1;
                int n = r % N;
                int t = r / N;
                int su = ((gi * KK + t) * Ctot + co0 + n) * 2 + q;
                int du = (t * N + n) * BPU4 + q;
                dstH[du] = srcH[su];
                dstL[du] = srcL[su];
            }
        }
        __syncthreads();

        // ---- compute: KK taps (R8-exact) ----
#pragma unroll
        for (int ky = 0; ky < K; ky++)
#pragma unroll
        for (int kx = 0; kx < K; kx++) {
            const int t = ky * K + kx;
            uint32_t aH[2][4], aL[2][4];
#pragma unroll
            for (int mt = 0; mt < 2; mt++) {
                int pixA = (2 * wid + mt + ky) * SWI + (qr + kx);
                uint2 h0 = *reinterpret_cast<const uint2*>(
                    &s_hi[pixA * APITCH + 4 * ql]);
                uint2 h1 = *reinterpret_cast<const uint2*>(
                    &s_hi[(pixA + 8) * APITCH + 4 * ql]);
                uint2 l0 = *reinterpret_cast<const uint2*>(
                    &s_lo[pixA * APITCH + 4 * ql]);
                uint2 l1 = *reinterpret_cast<const uint2*>(
                    &s_lo[(pixA + 8) * APITCH + 4 * ql]);
                aH[mt][0] = h0.x; aH[mt][1] = h1.x;
                aH[mt][2] = h0.y; aH[mt][3] = h1.y;
                aL[mt][0] = l0.x; aL[mt][1] = l1.x;
                aL[mt][2] = l0.y; aL[mt][3] = l1.y;
            }
#pragma unroll
            for (int nt = 0; nt < NT; nt++) {
                uint2 bh = *reinterpret_cast<const uint2*>(
                    &s_bh[(t * N + nt * 8 + qr) * BP16 + 4 * ql]);
                uint2 bl = *reinterpret_cast<const uint2*>(
                    &s_bl[(t * N + nt * 8 + qr) * BP16 + 4 * ql]);
#pragma unroll
                for (int mt = 0; mt < 2; mt++) {
                    mma_bf16(acc[mt][nt], aH[mt], bh.x, bh.y);
                    mma_bf16(acc[mt][nt], aH[mt], bl.x, bl.y);
                    mma_bf16(acc[mt][nt], aL[mt], bh.x, bh.y);
                }
            }
        }
    }

    // ---- epilogue ----
#pragma unroll
    for (int mt = 0; mt < 2; mt++) {
        int gy = y0 + 2 * wid + mt;
#pragma unroll
        for (int nt = 0; nt < NT; nt++) {
#pragma unroll
            for (int i = 0; i < 4; i++) {
                int co = co0 + nt * 8 + 2 * ql + (i & 1);
                int gx = x0 + qr + ((i >> 1) ? 8 : 0);
                float s = acc[mt][nt][i] + bias[co];
                if (ACT == ACT_RELU)      s = fmaxf(s, 0.f);
                else if (ACT == ACT_TANH) s = tanhf(s);
                else if (ACT == ACT_SIG)  s = 1.f / (1.f + expf(-s));
                out[((size_t)b * Ctot + co) * HW + (size_t)gy * W + gx] = s;
            }
        }
    }
}

// ===================================================================
// Scalar conv (R3 proven) for small deep layers.
// ===================================================================
template<int K, int COC, int ACT, int RPT>
__global__ void __launch_bounds__(128) conv_kernel(
    const float* __restrict__ inA, int CA,
    const float* __restrict__ inB, int CB,
    const float* __restrict__ wgt, const float* __restrict__ bias,
    float* __restrict__ out, int H, int W, int nChunk, int Ctot)
{
    constexpr int KK = K * K, PAD = K / 2, TH = 8 * RPT;
    constexpr int SW = (K == 3) ? 18 : 22;
    constexpr int SH = TH + K - 1;
    __shared__ float s_in[SH * SW];
    __shared__ __align__(16) float s_w[KK * COC];

    const int tx = threadIdx.x & 15, ty = threadIdx.x >> 4;
    const int x0 = blockIdx.x * 16, y0 = blockIdx.y * TH;
    const int z = blockIdx.z;
    const int b = z / nChunk, chunk = z - b * nChunk, co0 = chunk * COC;
    const int Cin = CA + CB;
    const size_t HW = (size_t)H * W;

    float acc[COC * RPT];
#pragma unroll
    for (int i = 0; i < COC * RPT; i++) acc[i] = 0.f;

    for (int cin = 0; cin < Cin; cin++) {
        const float* src = (cin < CA)
            ? inA + ((size_t)b * CA + cin) * HW
            : inB + ((size_t)b * CB + (cin - CA)) * HW;
        __syncthreads();
        for (int i = threadIdx.x; i < SH * SW; i += 128) {
            int iy = i / SW, ix = i - iy * SW;
            int gy = y0 + iy - PAD, gx = x0 + ix - PAD;
            float v = 0.f;
            if ((unsigned)gy < (unsigned)H && (unsigned)gx < (unsigned)W)
                v = src[(size_t)gy * W + gx];
            s_in[i] = v;
        }
        for (int i = threadIdx.x; i < KK * COC; i += 128) {
            int k = i / COC, co = i - k * COC;
            s_w[i] = wgt[((size_t)(co0 + co) * Cin + cin) * KK + k];
        }
        __syncthreads();

#pragma unroll
        for (int k = 0; k < KK; k++) {
            const int ky = k / K, kx = k - ky * K;
            float v[RPT];
#pragma unroll
            for (int r = 0; r < RPT; r++)
                v[r] = s_in[(ty + 8 * r + ky) * SW + tx + kx];
            if (COC % 4 == 0) {
#pragma unroll
                for (int c4 = 0; c4 < COC / 4; c4++) {
                    float4 w = *reinterpret_cast<const float4*>(&s_w[k * COC + 4 * c4]);
#pragma unroll
                    for (int r = 0; r < RPT; r++) {
                        acc[(4 * c4 + 0) * RPT + r] += v[r] * w.x;
                        acc[(4 * c4 + 1) * RPT + r] += v[r] * w.y;
                        acc[(4 * c4 + 2) * RPT + r] += v[r] * w.z;
                        acc[(4 * c4 + 3) * RPT + r] += v[r] * w.w;
                    }
                }
            } else {
#pragma unroll
                for (int co = 0; co < COC; co++) {
                    float w = s_w[k * COC + co];
#pragma unroll
                    for (int r = 0; r < RPT; r++)
                        acc[co * RPT + r] += v[r] * w;
                }
            }
        }
    }

    const int x = x0 + tx;
#pragma unroll
    for (int co = 0; co < COC; co++) {
        float bb = bias[co0 + co];
        size_t cbase = ((size_t)b * Ctot + co0 + co) * HW;
#pragma unroll
        for (int r = 0; r < RPT; r++) {
            float s = acc[co * RPT + r] + bb;
            if (ACT == ACT_RELU)      s = fmaxf(s, 0.f);
            else if (ACT == ACT_TANH) s = tanhf(s);
            else if (ACT == ACT_SIG)  s = 1.f / (1.f + expf(-s));
            out[cbase + (size_t)(y0 + ty + 8 * r) * W + x] = s;
        }
    }
}

__global__ void maxpool_kernel(const float* __restrict__ in,
                               float* __restrict__ out, int n, int Ho, int Wo)
{
    int idx = blockIdx.x * 256 + threadIdx.x;
    if (idx >= n) return;
    int x = idx % Wo, t = idx / Wo, y = t % Ho, bc = t / Ho;
    int Wi = Wo * 2;
    const float* p = in + ((size_t)bc * (Ho * 2) + 2 * y) * Wi + 2 * x;
    out[idx] = fmaxf(fmaxf(p[0], p[1]), fmaxf(p[Wi], p[Wi + 1]));
}

__global__ void upsample_kernel(const float* __restrict__ in,
                                float* __restrict__ out, int n, int Hi, int Wi)
{
    int idx = blockIdx.x * 256 + threadIdx.x;
    if (idx >= n) return;
    int Wo = Wi * 2, Ho = Hi * 2;
    int x = idx % Wo, t = idx / Wo, y = t % Ho, bc = t / Ho;
    int xi = x >> 1, yi = y >> 1;
    int xa, xb; float wxa;
    if (x & 1) { xa = xi; xb = min(xi + 1, Wi - 1); wxa = 0.75f; }
    else       { xa = max(xi - 1, 0); xb = xi;      wxa = 0.25f; }
    int ya, yb; float wya;
    if (y & 1) { ya = yi; yb = min(yi + 1, Hi - 1); wya = 0.75f; }
    else       { ya = max(yi - 1, 0); yb = yi;      wya = 0.25f; }
    const float* p = in + (size_t)bc * Hi * Wi;
    float r0 = wxa * p[ya * Wi + xa] + (1.f - wxa) * p[ya * Wi + xb];
    float r1 = wxa * p[yb * Wi + xa] + (1.f - wxa) * p[yb * Wi + xb];
    out[idx] = wya * r0 + (1.f - wya) * r1;
}

// ===================================================================
// LRNN horizontal: smem-transposed 32x32 chunks, fully coalesced.
// Block 256 thr: (b,c) = blockIdx.y, rows y0..y0+31 = blockIdx.x*32.
// Scan warp (tid<32) owns one row each, state held across chunks.
// ===================================================================
__global__ void __launch_bounds__(256) lrnn_h_kernel(
    const float* __restrict__ xin, const float* __restrict__ fm,
    float* __restrict__ out)
{
    __shared__ float tX[32][33], tXr[32][33];
    __shared__ float tP0[32][33], tP0r[32][33];
    __shared__ float tP2[32][33], tP2r[32][33];
    __shared__ float tO[32][33];

    const int bc = blockIdx.y;
    const int c = bc & 15, b = bc >> 4;
    const int y0 = blockIdx.x * 32;
    const float* X  = xin + (((size_t)b * 16 + c) << 16);
    const float* P0 = fm  + (((size_t)b * 64 + c)      << 16);
    const float* P2 = fm  + (((size_t)b * 64 + 32 + c) << 16);
    float* O        = out + (((size_t)b * 16 + c) << 16);

    const int tid  = threadIdx.x;
    const int lrow = tid >> 5;
    const int lcol = tid & 31;

    float h0 = 0.f, h1 = 0.f, h2 = 0.f, h3 = 0.f;
    for (int ck = 0; ck < 8; ck++) {
        int k0 = ck * 32;
        int j0 = 224 - k0;
        __syncthreads();
#pragma unroll
        for (int rr = 0; rr < 32; rr += 8) {
            int row = rr + lrow;
            int gb = (y0 + row) << 8;
            tX [row][lcol] = X [gb + k0 + lcol];
            tXr[row][lcol] = X [gb + j0 + lcol];
            tP0[row][lcol] = P0[gb + k0 + lcol];
            tP0r[row][lcol]= P0[gb + j0 + lcol];
            tP2[row][lcol] = P2[gb + k0 + lcol];
            tP2r[row][lcol]= P2[gb + j0 + lcol];
        }
        __syncthreads();
        if (tid < 32) {
            const int t = tid;
#pragma unroll
            for (int kk = 0; kk < 32; kk++) {
                float xf = tX[t][kk],        xb = tXr[t][31 - kk];
                float p0 = tP0[t][kk],       p1 = tP2[t][kk];
                float p2 = tP0r[t][31 - kk], p3 = tP2r[t][31 - kk];
                h0 = xf + p0 * (h0 - xf);
                h1 = xf + p1 * (h1 - xf);
                h2 = xb + p2 * (h2 - xb);
                h3 = xb + p3 * (h3 - xb);
                tO[t][kk] = fmaxf(fmaxf(h0, h1), fmaxf(h2, h3));
            }
        }
        __syncthreads();
#pragma unroll
        for (int rr = 0; rr < 32; rr += 8) {
            int row = rr + lrow;
            O[((y0 + row) << 8) + k0 + lcol] = tO[row][lcol];
        }
    }
}

__global__ void lrnn_v_kernel(const float* __restrict__ xin,
                              const float* __restrict__ fm,
                              float* __restrict__ out)
{
    int r = blockIdx.x * 256 + threadIdx.x;
    if (r >= 8 * 16 * 256) return;
    int x = r & 255, c = (r >> 8) & 15, b = r >> 12;
    const float* X  = xin + (((size_t)b * 16 + c) << 16) + x;
    const float* P1 = fm  + (((size_t)b * 64 + 16 + c) << 16) + x;
    const float* P3 = fm  + (((size_t)b * 64 + 48 + c) << 16) + x;
    float* O        = out + (((size_t)b * 16 + c) << 16) + x;
    float h0 = 0.f, h1 = 0.f, h2 = 0.f, h3 = 0.f;
    for (int k = 0; k < 256; k++) {
        int ko = k << 8, jo = (255 - k) << 8;
        float xf = X[ko], xb = X[jo];
        float p0 = P1[ko], p1 = P3[ko], p2 = P1[jo], p3 = P3[jo];
        h0 = xf + p0 * (h0 - xf);
        h1 = xf + p1 * (h1 - xf);
        h2 = xb + p2 * (h2 - xb);
        h3 = xb + p3 * (h3 - xb);
        float m = fmaxf(fmaxf(h0, h1), fmaxf(h2, h3));
        O[ko] = fmaxf(O[ko], m);
    }
}

extern "C" void kernel_launch(void* const* d_in, const int* in_sizes, int n_in,
                              void* d_out, int out_size)
{
    const float* img = (const float*)d_in[0];
    const float* w1 = (const float*)d_in[1],  *b1 = (const float*)d_in[2];
    const float* w2 = (const float*)d_in[3],  *b2 = (const float*)d_in[4];
    const float* w3 = (const float*)d_in[5],  *b3 = (const float*)d_in[6];
    const float* w4 = (const float*)d_in[7],  *b4 = (const float*)d_in[8];
    const float* w5 = (const float*)d_in[9],  *b5 = (const float*)d_in[10];
    const float* w6 = (const float*)d_in[11], *b6 = (const float*)d_in[12];
    const float* w7 = (const float*)d_in[13], *b7 = (const float*)d_in[14];
    const float* w8 = (const float*)d_in[15], *b8 = (const float*)d_in[16];
    const float* w9 = (const float*)d_in[17], *b9 = (const float*)d_in[18];
    const float* wi = (const float*)d_in[19], *bi = (const float*)d_in[20];
    const float* wo = (const float*)d_in[21], *bo = (const float*)d_in[22];
    float* outp = (float*)d_out;

    float* buf = nullptr;
    cudaGetSymbolAddress((void**)&buf, g_buf);
    float* X1 = buf + O_X1;  float* P1 = buf + O_P1;
    float* X2 = buf + O_X2;  float* P2 = buf + O_P2;
    float* X3 = buf + O_X3;  float* P3 = buf + O_P3;
    float* X4 = buf + O_X4;  float* P4 = buf + O_P4;
    float* X5 = buf + O_X5;  float* U5 = buf + O_U5;
    float* X6 = buf + O_X6;  float* U6 = buf + O_U6;
    float* X7 = buf + O_X7;  float* U7 = buf + O_U7;
    float* X8 = buf + O_X8;  float* U8 = buf + O_U8;
    float* FM = buf + O_FM;  float* XIN = buf + O_XIN;
    float* RMAX = buf + O_RMAX;
    uint16_t* wph = (uint16_t*)(buf + O_WP);
    uint16_t* wpl = wph + WPLANE;

    auto tg = [](int W, int H) { return dim3(W / 16, H / 8, 8); };
    auto cgrid = [](int W, int H, int RPT, int nChunk) {
        return dim3(W / 16, H / (8 * RPT), 8 * nChunk);
    };
    auto eg = [](size_t n) { return dim3((unsigned)((n + 255) / 256)); };
    auto pg = [](int n) { return dim3((n + 255) / 256); };

    // ---- weight prep (once per launch; tiny) ----
    prep_w_kernel<<<pg(1*25*16*16),256>>>(w1, wph+WOFF1, wpl+WOFF1, 15, 16, 25, 1*25*16*16);
    prep_w_kernel<<<pg(1*9*32*16),256>>>(w2, wph+WOFF2, wpl+WOFF2, 16, 32, 9, 1*9*32*16);
    prep_w_kernel<<<pg(2*9*32*16),256>>>(w3, wph+WOFF3, wpl+WOFF3, 32, 32, 9, 2*9*32*16);
    prep_w_kernel<<<pg(4*9*32*16),256>>>(w7, wph+WOFF7, wpl+WOFF7, 64, 32, 9, 4*9*32*16);
    prep_w_kernel<<<pg(4*9*32*16),256>>>(w8, wph+WOFF8, wpl+WOFF8, 64, 32, 9, 4*9*32*16);
    prep_w_kernel<<<pg(3*9*64*16),256>>>(w9, wph+WOFF9, wpl+WOFF9, 48, 64, 9, 3*9*64*16);
    prep_w_kernel<<<pg(1*9*16*16),256>>>(wi, wph+WOFFI, wpl+WOFFI, 15, 16, 9, 1*9*16*16);

    // encoder
    tconv_kernel<5,16,ACT_RELU><<<tg(256,256),128>>>(img,15, nullptr,0, wph+WOFF1,wpl+WOFF1, b1, X1, 256,256, 0,16);
    maxpool_kernel<<<eg(N_P1),256>>>(X1, P1, (int)N_P1, 128,128);
    tconv_kernel<3,32,ACT_RELU><<<tg(128,128),128>>>(P1,16, nullptr,0, wph+WOFF2,wpl+WOFF2, b2, X2, 128,128, 0,32);
    maxpool_kernel<<<eg(N_P2),256>>>(X2, P2, (int)N_P2, 64,64);
    tconv_kernel<3,32,ACT_RELU><<<tg(64,64),128>>>(P2,32, nullptr,0, wph+WOFF3,wpl+WOFF3, b3, X3, 64,64, 0,32);
    maxpool_kernel<<<eg(N_P3),256>>>(X3, P3, (int)N_P3, 32,32);
    conv_kernel<3,16,ACT_RELU,1><<<cgrid(32,32,1,2),128>>>(P3,32, nullptr,0, w4,b4, X4, 32,32, 2,32);
    maxpool_kernel<<<eg(N_P4),256>>>(X4, P4, (int)N_P4, 16,16);
    conv_kernel<3,16,ACT_RELU,1><<<cgrid(16,16,1,4),128>>>(P4,32, nullptr,0, w5,b5, X5, 16,16, 4,64);

    // decoder
    upsample_kernel<<<eg(N_U5),256>>>(X5, U5, (int)N_U5, 16,16);
    conv_kernel<3,16,ACT_RELU,1><<<cgrid(32,32,1,2),128>>>(U5,64, X4,32, w6,b6, X6, 32,32, 2,32);
    upsample_kernel<<<eg(N_U6),256>>>(X6, U6, (int)N_U6, 32,32);
    tconv_kernel<3,32,ACT_RELU><<<tg(64,64),128>>>(U6,32, X3,32, wph+WOFF7,wpl+WOFF7, b7, X7, 64,64, 0,32);
    upsample_kernel<<<eg(N_U7),256>>>(X7, U7, (int)N_U7, 64,64);
    tconv_kernel<3,32,ACT_RELU><<<tg(128,128),128>>>(U7,32, X2,32, wph+WOFF8,wpl+WOFF8, b8, X8, 128,128, 0,32);
    upsample_kernel<<<eg(N_U8),256>>>(X8, U8, (int)N_U8, 128,128);
    tconv_kernel<3,32,ACT_TANH><<<tg(256,256),128>>>(U8,32, X1,16, wph+WOFF9,wpl+WOFF9, b9, FM, 256,256, 0,64);
    tconv_kernel<3,32,ACT_TANH><<<tg(256,256),128>>>(U8,32, X1,16, wph+WOFF9,wpl+WOFF9, b9, FM, 256,256, 32,64);

    // input projection
    tconv_kernel<3,16,ACT_NONE><<<tg(256,256),128>>>(img,15, nullptr,0, wph+WOFFI,wpl+WOFFI, bi, XIN, 256,256, 0,16);

    // spatial RNN
    lrnn_h_kernel<<<dim3(8,128),256>>>(XIN, FM, RMAX);
    lrnn_v_kernel<<<128,256>>>(XIN, FM, RMAX);

    // output conv + sigmoid (scalar)
    conv_kernel<3,3,ACT_SIG,4><<<cgrid(256,256,4,1),128>>>(RMAX,16, nullptr,0, wo,bo, outp, 256,256, 1,3);
}